// round 10
// baseline (speedup 1.0000x reference)
#include <cuda_runtime.h>
#include <cuda_bf16.h>
#include <cstdint>
#include <math.h>

// ---------------------------------------------------------------------------
// HyenaOperator2d:  B=4, S=128, D=256, d3=768, L=16384, FO=64
// Tensor-core mma.sync bf16 hi/lo split (3 MMAs per fp32 product).
// n-fast grids (L2 reuse), pre-split x, row-parallel dwconv.
// ---------------------------------------------------------------------------

#define PI_F 3.14159265358979f
#define MIN_D (-3.0701134573253943f)
#define MAX_D (-15.350567286626972f)

__device__ float g_hxT[256 * 128];            // [d][s], includes *dec*(1/256)
__device__ float g_hyT[256 * 128];            // [d][s], includes *dec
__device__ float g_U [50331648];              // (b,768,16384) planar
__device__ float g_x0[16777216];              // (b,256,16384) planar
__device__ float g_vg[16777216];
__device__ float g_g [16777216];              // toep output, planar (b,d,l)

__device__ __nv_bfloat16 g_xhi[65536 * 256];      // x split, row-major [m][k]
__device__ __nv_bfloat16 g_xlo[65536 * 256];
__device__ __nv_bfloat16 g_inwT_hi [768 * 256];   // [n][k]
__device__ __nv_bfloat16 g_inwT_lo [768 * 256];
__device__ __nv_bfloat16 g_outwT_hi[256 * 256];   // [n][k]
__device__ __nv_bfloat16 g_outwT_lo[256 * 256];

// ---- helpers ---------------------------------------------------------------
__device__ __forceinline__ uint32_t smem_u32(const void* p) {
    uint32_t a;
    asm("{ .reg .u64 t; cvta.to.shared.u64 t, %1; cvt.u32.u64 %0, t; }"
        : "=r"(a) : "l"(p));
    return a;
}
__device__ __forceinline__ void split_bf16(float v, unsigned short& hi, unsigned short& lo) {
    __nv_bfloat16 h = __float2bfloat16(v);
    __nv_bfloat16 l = __float2bfloat16(v - __bfloat162float(h));
    hi = __bfloat16_as_ushort(h);
    lo = __bfloat16_as_ushort(l);
}
__device__ __forceinline__ void split4(float4 v, uint2& hv, uint2& lv) {
    unsigned short h0,h1,h2,h3,l0,l1,l2,l3;
    split_bf16(v.x, h0, l0); split_bf16(v.y, h1, l1);
    split_bf16(v.z, h2, l2); split_bf16(v.w, h3, l3);
    hv.x = ((uint32_t)h1 << 16) | h0;  hv.y = ((uint32_t)h3 << 16) | h2;
    lv.x = ((uint32_t)l1 << 16) | l0;  lv.y = ((uint32_t)l3 << 16) | l2;
}
__device__ __forceinline__ void ldsm4(uint32_t* r, uint32_t addr) {
    asm volatile("ldmatrix.sync.aligned.m8n8.x4.shared.b16 {%0,%1,%2,%3}, [%4];"
        : "=r"(r[0]), "=r"(r[1]), "=r"(r[2]), "=r"(r[3]) : "r"(addr));
}
__device__ __forceinline__ void mma_bf16(float* d, const uint32_t* a, const uint32_t* b) {
    asm volatile(
        "mma.sync.aligned.m16n8k16.row.col.f32.bf16.bf16.f32 "
        "{%0,%1,%2,%3}, {%4,%5,%6,%7}, {%8,%9}, {%0,%1,%2,%3};"
        : "+f"(d[0]), "+f"(d[1]), "+f"(d[2]), "+f"(d[3])
        : "r"(a[0]), "r"(a[1]), "r"(a[2]), "r"(a[3]), "r"(b[0]), "r"(b[1]));
}

// Warp-tile 64x32 split-bf16 MMA over staged K panel (nk16 steps of k=16).
template <int AST, int BST>
__device__ __forceinline__ void mma_panel(
    float acc[4][4][4],
    uint32_t ah, uint32_t al, uint32_t bh, uint32_t bl,
    int lane, int nk16)
{
    const int sub = lane >> 3, r = lane & 7;
    const int am = (sub & 1) * 8 + r;
    const int ak = (sub >> 1) * 8;
    const int bn = (sub >> 1) * 8 + r;
    const int bk = (sub & 1) * 8;
    for (int ks = 0; ks < nk16; ks++) {
        uint32_t AH[4][4], AL[4][4], BH[4][2], BL[4][2];
        #pragma unroll
        for (int mt = 0; mt < 4; mt++) {
            uint32_t off = (uint32_t)((mt * 16 + am) * AST + (ks * 16 + ak) * 2);
            ldsm4(AH[mt], ah + off);
            ldsm4(AL[mt], al + off);
        }
        #pragma unroll
        for (int np = 0; np < 2; np++) {
            uint32_t u[4];
            uint32_t off = (uint32_t)((np * 16 + bn) * BST + (ks * 16 + bk) * 2);
            ldsm4(u, bh + off);
            BH[2*np][0] = u[0]; BH[2*np][1] = u[1];
            BH[2*np+1][0] = u[2]; BH[2*np+1][1] = u[3];
            ldsm4(u, bl + off);
            BL[2*np][0] = u[0]; BL[2*np][1] = u[1];
            BL[2*np+1][0] = u[2]; BL[2*np+1][1] = u[3];
        }
        #pragma unroll
        for (int mt = 0; mt < 4; mt++)
            #pragma unroll
            for (int nt = 0; nt < 4; nt++) {
                mma_bf16(acc[mt][nt], AH[mt], BH[nt]);
                mma_bf16(acc[mt][nt], AH[mt], BL[nt]);
                mma_bf16(acc[mt][nt], AL[mt], BH[nt]);
            }
    }
}

// ---------------------------------------------------------------------------
// Implicit filter MLPs + positional embedding + decay. 128 blocks (s), 64 thr.
// ---------------------------------------------------------------------------
__global__ void filter_kernel(
    const float* __restrict__ freq,
    const float* __restrict__ xw0, const float* __restrict__ xb0,
    const float* __restrict__ xw1, const float* __restrict__ xb1,
    const float* __restrict__ xw2, const float* __restrict__ xb2,
    const float* __restrict__ xw3,
    const float* __restrict__ yw0, const float* __restrict__ yb0,
    const float* __restrict__ yw1, const float* __restrict__ yb1,
    const float* __restrict__ yw2, const float* __restrict__ yb2,
    const float* __restrict__ yw3)
{
    __shared__ float h[64];
    const int s = blockIdx.x;
    const int j = threadIdx.x;

    const float t   = (float)s / 127.0f;
    const float phi = 1e-4f * 2.0f * PI_F * (float)s / 128.0f;
    const float z0 = t, z1 = cosf(phi), z2 = -sinf(phi);
    const float fr = freq[j];

    for (int which = 0; which < 2; which++) {
        const float* w0 = which ? yw0 : xw0;  const float* b0 = which ? yb0 : xb0;
        const float* w1 = which ? yw1 : xw1;  const float* b1 = which ? yb1 : xb1;
        const float* w2 = which ? yw2 : xw2;  const float* b2 = which ? yb2 : xb2;
        const float* w3 = which ? yw3 : xw3;

        float v = z0 * w0[j] + z1 * w0[64 + j] + z2 * w0[128 + j] + b0[j];
        h[j] = sinf(fr * v);
        __syncthreads();

        float a = b1[j];
        #pragma unroll 8
        for (int k = 0; k < 64; k++) a += h[k] * w1[k * 64 + j];
        __syncthreads();
        h[j] = sinf(fr * a);
        __syncthreads();

        a = b2[j];
        #pragma unroll 8
        for (int k = 0; k < 64; k++) a += h[k] * w2[k * 64 + j];
        __syncthreads();
        h[j] = sinf(fr * a);
        __syncthreads();

        float o[4] = {0.f, 0.f, 0.f, 0.f};
        #pragma unroll 8
        for (int k = 0; k < 64; k++) {
            float hv = h[k];
            #pragma unroll
            for (int r = 0; r < 4; r++) o[r] += hv * w3[k * 256 + j + 64 * r];
        }
        #pragma unroll
        for (int r = 0; r < 4; r++) {
            int d = j + 64 * r;
            float delta = MIN_D + (MAX_D - MIN_D) * ((float)d / 255.0f);
            float dec = expf(-t * fabsf(delta));
            if (which == 0)
                g_hxT[d * 128 + s] = o[r] * dec * (1.0f / 256.0f);
            else
                g_hyT[d * 128 + s] = o[r] * dec;
        }
        __syncthreads();
    }
}

// ---------------------------------------------------------------------------
// x -> bf16 hi/lo split (row-major).  grid 16384 x 256.
// ---------------------------------------------------------------------------
__global__ __launch_bounds__(256) void xsplit_kernel(const float* __restrict__ X)
{
    size_t i = (size_t)blockIdx.x * 256 + threadIdx.x;
    float4 v = *(const float4*)(X + i * 4);
    uint2 hv, lv;
    split4(v, hv, lv);
    *(uint2*)(g_xhi + i * 4) = hv;
    *(uint2*)(g_xlo + i * 4) = lv;
}

// ---------------------------------------------------------------------------
// Tiled transpose + bf16 hi/lo split for weights.
// ---------------------------------------------------------------------------
__device__ __forceinline__ void do_tsplit(
    const float* __restrict__ src, __nv_bfloat16* __restrict__ dhi,
    __nv_bfloat16* __restrict__ dlo, int rows, int cols)
{
    __shared__ float tile[32][33];
    const int c0 = blockIdx.x * 32, r0 = blockIdx.y * 32;
    const int tx = threadIdx.x, ty = threadIdx.y;
    #pragma unroll
    for (int i = 0; i < 4; i++)
        tile[ty + 8 * i][tx] = src[(size_t)(r0 + ty + 8 * i) * cols + c0 + tx];
    __syncthreads();
    #pragma unroll
    for (int i = 0; i < 4; i++) {
        float v = tile[tx][ty + 8 * i];
        unsigned short hi, lo;
        split_bf16(v, hi, lo);
        size_t o = (size_t)(c0 + ty + 8 * i) * rows + r0 + tx;
        dhi[o] = __ushort_as_bfloat16(hi);
        dlo[o] = __ushort_as_bfloat16(lo);
    }
}
__global__ void tsplit_inw_kernel(const float* __restrict__ w) {
    do_tsplit(w, g_inwT_hi, g_inwT_lo, 256, 768);
}
__global__ void tsplit_outw_kernel(const float* __restrict__ w) {
    do_tsplit(w, g_outwT_hi, g_outwT_lo, 256, 256);
}

// ---------------------------------------------------------------------------
// GEMM1: U(b,c,l) = x @ in_w + in_b.  M=65536 K=256 N=768.
// grid(6,512) n-fast; A and B both pre-split bf16 (pure uint4 staging).
// ---------------------------------------------------------------------------
#define G1_SMEM 66048

__global__ __launch_bounds__(256) void gemm1_mma(const float* __restrict__ bias)
{
    extern __shared__ __align__(16) char sm[];
    const uint32_t smb = smem_u32(sm);
    const int tid = threadIdx.x, lane = tid & 31, wid = tid >> 5;
    const int wm = wid & 1, wn = wid >> 1;
    const int m0 = blockIdx.y * 128, n0 = blockIdx.x * 128;

    float acc[4][4][4];
    #pragma unroll
    for (int a = 0; a < 4; a++)
        #pragma unroll
        for (int b = 0; b < 4; b++)
            #pragma unroll
            for (int c = 0; c < 4; c++) acc[a][b][c] = 0.f;

    for (int kt = 0; kt < 8; kt++) {
        const int k0 = kt * 32;
        __syncthreads();
        // A: pre-split x hi/lo (uint4 copies, 128 rows x 32 k)
        #pragma unroll
        for (int e = tid; e < 512; e += 256) {
            int r = e >> 2, q = e & 3;
            size_t ga = (size_t)(m0 + r) * 256 + k0 + q * 8;
            *(uint4*)(sm +         r * 80 + q * 16) = *(const uint4*)(g_xhi + ga);
            *(uint4*)(sm + 10240 + r * 80 + q * 16) = *(const uint4*)(g_xlo + ga);
        }
        // B: precomputed in_wT hi/lo
        #pragma unroll
        for (int e = tid; e < 512; e += 256) {
            int r = e >> 2, q = e & 3;
            size_t gb = (size_t)(n0 + r) * 256 + k0 + q * 8;
            *(uint4*)(sm + 20480 + r * 80 + q * 16) = *(const uint4*)(g_inwT_hi + gb);
            *(uint4*)(sm + 30720 + r * 80 + q * 16) = *(const uint4*)(g_inwT_lo + gb);
        }
        __syncthreads();
        mma_panel<80, 80>(acc, smb + wm * 64 * 80, smb + 10240 + wm * 64 * 80,
                          smb + 20480 + wn * 32 * 80, smb + 30720 + wn * 32 * 80,
                          lane, 2);
    }

    __syncthreads();
    float* stg = (float*)sm;
    #pragma unroll
    for (int mt = 0; mt < 4; mt++)
        #pragma unroll
        for (int nt = 0; nt < 4; nt++) {
            int m = wm * 64 + mt * 16 + (lane >> 2);
            int n = wn * 32 + nt * 8 + 2 * (lane & 3);
            stg[m * 129 + n]           = acc[mt][nt][0];
            stg[m * 129 + n + 1]       = acc[mt][nt][1];
            stg[(m + 8) * 129 + n]     = acc[mt][nt][2];
            stg[(m + 8) * 129 + n + 1] = acc[mt][nt][3];
        }
    __syncthreads();
    const int b = m0 >> 14;
    const int l0 = m0 & 16383;
    const int mloc = tid & 63;
    #pragma unroll
    for (int j = 0; j < 32; j++) {
        int n = j * 4 + (tid >> 6);
        float bb = __ldg(bias + n0 + n);
        float* dst = g_U + ((size_t)(b * 768 + n0 + n) << 14) + l0;
        dst[mloc]      = stg[mloc * 129 + n] + bb;
        dst[mloc + 64] = stg[(mloc + 64) * 129 + n] + bb;
    }
}

// ---------------------------------------------------------------------------
// GEMM2: out(b,l,n) = g(b,d,l)^T @ out_wT + out_b.  grid(2,128,4) n-fast.
// ---------------------------------------------------------------------------
#define G2_SMEM 40960

__global__ __launch_bounds__(256) void gemm2_mma(
    const float* __restrict__ bias, float* __restrict__ Out)
{
    extern __shared__ __align__(16) char sm[];
    const uint32_t smb = smem_u32(sm);
    const int tid = threadIdx.x, lane = tid & 31, wid = tid >> 5;
    const int wm = wid & 1, wn = wid >> 1;
    const int m0 = blockIdx.y * 128, n0 = blockIdx.x * 128;
    const int b = blockIdx.z;
    const float* Gb = g_g + ((size_t)b << 22);

    float acc[4][4][4];
    #pragma unroll
    for (int a = 0; a < 4; a++)
        #pragma unroll
        for (int c = 0; c < 4; c++)
            #pragma unroll
            for (int e = 0; e < 4; e++) acc[a][c][e] = 0.f;

    for (int kt = 0; kt < 8; kt++) {
        const int k0 = kt * 32;
        __syncthreads();
        // A: transpose+split from planar g: A[m=l][k=d]
        #pragma unroll
        for (int e = tid; e < 1024; e += 256) {
            int lloc = e & 127, dq = e >> 7;
            unsigned short h[4], l[4];
            #pragma unroll
            for (int t = 0; t < 4; t++) {
                float v = Gb[((size_t)(k0 + dq * 4 + t) << 14) + m0 + lloc];
                split_bf16(v, h[t], l[t]);
            }
            uint2 hv, lv;
            hv.x = ((uint32_t)h[1] << 16) | h[0];  hv.y = ((uint32_t)h[3] << 16) | h[2];
            lv.x = ((uint32_t)l[1] << 16) | l[0];  lv.y = ((uint32_t)l[3] << 16) | l[2];
            *(uint2*)(sm +         lloc * 80 + dq * 8) = hv;
            *(uint2*)(sm + 10240 + lloc * 80 + dq * 8) = lv;
        }
        // B: precomputed out_wT hi/lo
        #pragma unroll
        for (int e = tid; e < 512; e += 256) {
            int r = e >> 2, q = e & 3;
            size_t gb = (size_t)(n0 + r) * 256 + k0 + q * 8;
            *(uint4*)(sm + 20480 + r * 80 + q * 16) = *(const uint4*)(g_outwT_hi + gb);
            *(uint4*)(sm + 30720 + r * 80 + q * 16) = *(const uint4*)(g_outwT_lo + gb);
        }
        __syncthreads();
        mma_panel<80, 80>(acc, smb + wm * 64 * 80, smb + 10240 + wm * 64 * 80,
                          smb + 20480 + wn * 32 * 80, smb + 30720 + wn * 32 * 80,
                          lane, 2);
    }

    #pragma unroll
    for (int mt = 0; mt < 4; mt++)
        #pragma unroll
        for (int nt = 0; nt < 4; nt++) {
            int m = m0 + wm * 64 + mt * 16 + (lane >> 2);
            int n = n0 + wn * 32 + nt * 8 + 2 * (lane & 3);
            float2 bb = *(const float2*)&bias[n];
            float2 v0 = { acc[mt][nt][0] + bb.x, acc[mt][nt][1] + bb.y };
            float2 v1 = { acc[mt][nt][2] + bb.x, acc[mt][nt][3] + bb.y };
            *(float2*)&Out[(((size_t)b << 14) + m) * 256 + n] = v0;
            *(float2*)&Out[(((size_t)b << 14) + m + 8) * 256 + n] = v1;
        }
}

// ---------------------------------------------------------------------------
// Depthwise 3x3 conv, float4 + shfl, 4 row-chunks per plane-task.
// grid 8192 x 32: block = (bd, which, chunk); chunk handles rows 32c..32c+31.
// ---------------------------------------------------------------------------
__device__ __forceinline__ float4 hconv(float4 c, float m1, float m2,
                                        float w0, float w1, float w2) {
    float4 o;
    o.x = w0 * m2  + w1 * m1  + w2 * c.x;
    o.y = w0 * m1  + w1 * c.x + w2 * c.y;
    o.z = w0 * c.x + w1 * c.y + w2 * c.z;
    o.w = w0 * c.y + w1 * c.z + w2 * c.w;
    return o;
}
__device__ __forceinline__ void lnbr(float4 c, int lane, float& m1, float& m2) {
    m1 = __shfl_up_sync(0xFFFFFFFFu, c.w, 1);
    m2 = __shfl_up_sync(0xFFFFFFFFu, c.z, 1);
    if (lane == 0) { m1 = 0.f; m2 = 0.f; }
}

__global__ __launch_bounds__(32) void dwconv_kernel(
    const float* __restrict__ sfw, const float* __restrict__ sfb)
{
    const int blk = blockIdx.x;
    const int chunk = blk & 3;
    const int which = (blk >> 2) & 1;
    const int bd = blk >> 3;
    const int b = bd >> 8, d = bd & 255;
    const int lane = threadIdx.x;
    const size_t outp = (size_t)bd << 14;
    const int r0 = chunk * 32;

    if (which == 0) {
        const float* p = g_U + ((size_t)(b * 768 + d) << 14);
        float w[9];
        #pragma unroll
        for (int q = 0; q < 9; q++) w[q] = sfw[d * 9 + q];
        const float bs = sfb[d];
        float4 av = {0,0,0,0}, rv = {0,0,0,0};
        float am1 = 0, am2 = 0, rm1 = 0, rm2 = 0;
        if (chunk > 0) {
            av = *(const float4*)(p + (r0 - 2) * 128 + lane * 4);
            lnbr(av, lane, am1, am2);
            rv = *(const float4*)(p + (r0 - 1) * 128 + lane * 4);
            lnbr(rv, lane, rm1, rm2);
        }
        for (int i = r0; i < r0 + 32; i++) {
            float4 cv = *(const float4*)(p + i * 128 + lane * 4);
            float cm1, cm2;
            lnbr(cv, lane, cm1, cm2);
            float4 o = hconv(av, am1, am2, w[0], w[1], w[2]);
            float4 o2 = hconv(rv, rm1, rm2, w[3], w[4], w[5]);
            float4 o3 = hconv(cv, cm1, cm2, w[6], w[7], w[8]);
            float4 r;
            r.x = bs + o.x + o2.x + o3.x;
            r.y = bs + o.y + o2.y + o3.y;
            r.z = bs + o.z + o2.z + o3.z;
            r.w = bs + o.w + o2.w + o3.w;
            *(float4*)(g_x0 + outp + i * 128 + lane * 4) = r;
            av = rv; am1 = rm1; am2 = rm2;
            rv = cv; rm1 = cm1; rm2 = cm2;
        }
    } else {
        const float* p1 = g_U + ((size_t)(b * 768 + 256 + d) << 14);
        const float* p2 = g_U + ((size_t)(b * 768 + 512 + d) << 14);
        float w1[9], w2[9];
        #pragma unroll
        for (int q = 0; q < 9; q++) {
            w1[q] = sfw[(256 + d) * 9 + q];
            w2[q] = sfw[(512 + d) * 9 + q];
        }
        const float bs1 = sfb[256 + d], bs2 = sfb[512 + d];
        float4 av1 = {0,0,0,0}, rv1 = {0,0,0,0}, av2 = {0,0,0,0}, rv2 = {0,0,0,0};
        float am11=0, am12=0, rm11=0, rm12=0, am21=0, am22=0, rm21=0, rm22=0;
        if (chunk > 0) {
            av1 = *(const float4*)(p1 + (r0 - 2) * 128 + lane * 4);
            lnbr(av1, lane, am11, am12);
            rv1 = *(const float4*)(p1 + (r0 - 1) * 128 + lane * 4);
            lnbr(rv1, lane, rm11, rm12);
            av2 = *(const float4*)(p2 + (r0 - 2) * 128 + lane * 4);
            lnbr(av2, lane, am21, am22);
            rv2 = *(const float4*)(p2 + (r0 - 1) * 128 + lane * 4);
            lnbr(rv2, lane, rm21, rm22);
        }
        for (int i = r0; i < r0 + 32; i++) {
            float4 cv1 = *(const float4*)(p1 + i * 128 + lane * 4);
            float4 cv2 = *(const float4*)(p2 + i * 128 + lane * 4);
            float cm11, cm12, cm21, cm22;
            lnbr(cv1, lane, cm11, cm12);
            lnbr(cv2, lane, cm21, cm22);
            float4 oa = hconv(av1, am11, am12, w1[0], w1[1], w1[2]);
            float4 ob = hconv(rv1, rm11, rm12, w1[3], w1[4], w1[5]);
            float4 oc = hconv(cv1, cm11, cm12, w1[6], w1[7], w1[8]);
            float4 pa = hconv(av2, am21, am22, w2[0], w2[1], w2[2]);
            float4 pb = hconv(rv2, rm21, rm22, w2[3], w2[4], w2[5]);
            float4 pc = hconv(cv2, cm21, cm22, w2[6], w2[7], w2[8]);
            float4 r;
            r.x = (bs1 + oa.x + ob.x + oc.x) * (bs2 + pa.x + pb.x + pc.x);
            r.y = (bs1 + oa.y + ob.y + oc.y) * (bs2 + pa.y + pb.y + pc.y);
            r.z = (bs1 + oa.z + ob.z + oc.z) * (bs2 + pa.z + pb.z + pc.z);
            r.w = (bs1 + oa.w + ob.w + oc.w) * (bs2 + pa.w + pb.w + pc.w);
            *(float4*)(g_vg + outp + i * 128 + lane * 4) = r;
            av1 = rv1; am11 = rm11; am12 = rm12;
            rv1 = cv1; rm11 = cm11; rm12 = cm12;
            av2 = rv2; am21 = rm21; am22 = rm22;
            rv2 = cv2; rm21 = cm21; rm22 = cm22;
        }
    }
}

// ---------------------------------------------------------------------------
// Fused Toeplitz, 2 CTAs/SM (109KB smem). Chunked staging, persistent W1.
// ---------------------------------------------------------------------------
#define TW_W1H 0
#define TW_W1L 34816
#define TW_AH  69632
#define TW_AL  79872
#define TW_BH  90112
#define TW_BL  100352
#define TW_HV  110592
#define TW_SMEM 111616

__global__ __launch_bounds__(256) void toep_mma(const float* __restrict__ fbias)
{
    extern __shared__ __align__(16) char sm[];
    const uint32_t smb = smem_u32(sm);
    float* hxs = (float*)(sm + TW_HV);
    float* hys = hxs + 128;
    const int tid = threadIdx.x, lane = tid & 31, wid = tid >> 5;
    const int wm = wid & 1, wn = wid >> 1;
    const int bd = blockIdx.x;
    const int d = bd & 255;
    const float* vgp = g_vg + ((size_t)bd << 14);
    const int aq = tid & 7, ar0 = tid >> 3;

    if (tid < 128) {
        hxs[tid] = g_hxT[d * 128 + tid];
        hys[tid] = g_hyT[d * 128 + tid];
    }
    __syncthreads();

    float acc[4][4][4];
    #pragma unroll
    for (int a = 0; a < 4; a++)
        #pragma unroll
        for (int b = 0; b < 4; b++)
            #pragma unroll
            for (int c = 0; c < 4; c++) acc[a][b][c] = 0.f;

    // ---- pass 1: W1 = VG @ T(hy), 4 chunks of k=32 ----
    for (int kc = 0; kc < 4; kc++) {
        if (kc > 0) __syncthreads();
        #pragma unroll
        for (int i = 0; i < 4; i++) {
            int r = ar0 + 32 * i;
            int c = kc * 32 + aq * 4;
            float4 v = *(const float4*)(vgp + r * 128 + c);
            uint2 hv, lv;
            split4(v, hv, lv);
            *(uint2*)(sm + TW_AH + r * 80 + aq * 8) = hv;
            *(uint2*)(sm + TW_AL + r * 80 + aq * 8) = lv;
            float4 t;
            t.x = (r - c     >= 0) ? hys[r - c]     : 0.f;
            t.y = (r - c - 1 >= 0) ? hys[r - c - 1] : 0.f;
            t.z = (r - c - 2 >= 0) ? hys[r - c - 2] : 0.f;
            t.w = (r - c - 3 >= 0) ? hys[r - c - 3] : 0.f;
            split4(t, hv, lv);
            *(uint2*)(sm + TW_BH + r * 80 + aq * 8) = hv;
            *(uint2*)(sm + TW_BL + r * 80 + aq * 8) = lv;
        }
        __syncthreads();
        mma_panel<80, 80>(acc,
            smb + TW_AH + wm * 64 * 80, smb + TW_AL + wm * 64 * 80,
            smb + TW_BH + wn * 32 * 80, smb + TW_BL + wn * 32 * 80, lane, 2);
    }
    __syncthreads();

    // W1^T split -> persistent W1 region (stride 136)
    __nv_bfloat16* bh = (__nv_bfloat16*)(sm + TW_W1H);
    __nv_bfloat16* bl = (__nv_bfloat16*)(sm + TW_W1L);
    #pragma unroll
    for (int mt = 0; mt < 4; mt++)
        #pragma unroll
        for (int nt = 0; nt < 4; nt++) {
            int m = wm * 64 + mt * 16 + (lane >> 2);
            int n = wn * 32 + nt * 8 + 2 * (lane & 3);
            unsigned short h, l;
            split_bf16(acc[mt][nt][0], h, l);
            bh[n * 136 + m] = __ushort_as_bfloat16(h);
            bl[n * 136 + m] = __ushort_as_bfloat16(l);
            split_bf16(acc[mt][nt][1], h, l);
            bh[(n + 1) * 136 + m] = __ushort_as_bfloat16(h);
            bl[(n + 1) * 136 + m] = __ushort_as_bfloat16(l);
            split_bf16(acc[mt][nt][2], h, l);
            bh[n * 136 + m + 8] = __ushort_as_bfloat16(h);
            bl[n * 136 + m + 8] = __ushort_as_bfloat16(l);
            split_bf16(acc[mt][nt][3], h, l);
            bh[(n + 1) * 136 + m + 8] = __ushort_as_bfloat16(h);
            bl[(n + 1) * 136 + m + 8] = __ushort_as_bfloat16(l);
            acc[mt][nt][0] = acc[mt][nt][1] = acc[mt][nt][2] = acc[mt][nt][3] = 0.f;
        }

    // ---- pass 2: C = T(hx) @ W1 ----
    for (int kc = 0; kc < 4; kc++) {
        __syncthreads();
        #pragma unroll
        for (int i = 0; i < 4; i++) {
            int r = ar0 + 32 * i;
            int c = kc * 32 + aq * 4;
            float4 t;
            t.x = (r - c     >= 0) ? hxs[r - c]     : 0.f;
            t.y = (r - c - 1 >= 0) ? hxs[r - c - 1] : 0.f;
            t.z = (r - c - 2 >= 0) ? hxs[r - c - 2] : 0.f;
            t.w = (r - c - 3 >= 0) ? hxs[r - c - 3] : 0.f;
            uint2 hv, lv;
            split4(t, hv, lv);
            *(uint2*)(sm + TW_AH + r * 80 + aq * 8) = hv;
            *(uint2*)(sm + TW_AL + r * 80 + aq * 8) = lv;
        }
        __syncthreads();
        mma_panel<80, 272>(acc,
            smb + TW_AH + wm * 64 * 80, smb + TW_AL + wm * 64 * 80,
            smb + TW_W1H + wn * 32 * 272 + kc * 64,
            smb + TW_W1L + wn * 32 * 272 + kc * 64, lane, 2);
    }

    // epilogue: g = (C + vg*fb) * x0
    const float fb = fbias[d];
    const float* x0p = g_x0 + ((size_t)bd << 14);
    float* gp = g_g + ((size_t)bd << 14);
    #pragma unroll
    for (int mt = 0; mt < 4; mt++)
        #pragma unroll
        for (int nt = 0; nt < 4; nt++) {
            int m = wm * 64 + mt * 16 + (lane >> 2);
            int n = wn * 32 + nt * 8 + 2 * (lane & 3);
            #pragma unroll
            for (int half = 0; half < 2; half++) {
                int idx = (m + 8 * half) * 128 + n;
                float2 c = { acc[mt][nt][2 * half], acc[mt][nt][2 * half + 1] };
                float2 v = *(const float2*)(vgp + idx);
                float2 x = *(const float2*)(x0p + idx);
                float2 r;
                r.x = (c.x + v.x * fb) * x.x;
                r.y = (c.y + v.y * fb) * x.y;
                *(float2*)(gp + idx) = r;
            }
        }
}

// ---------------------------------------------------------------------------
extern "C" void kernel_launch(void* const* d_in, const int* in_sizes, int n_in,
                              void* d_out, int out_size)
{
    (void)in_sizes; (void)n_in; (void)out_size;
    const float* x     = (const float*)d_in[0];
    const float* in_w  = (const float*)d_in[1];
    const float* in_b  = (const float*)d_in[2];
    const float* out_w = (const float*)d_in[3];
    const float* out_b = (const float*)d_in[4];
    const float* sf_w  = (const float*)d_in[5];
    const float* sf_b  = (const float*)d_in[6];
    const float* freq  = (const float*)d_in[7];
    const float* xw0 = (const float*)d_in[8];
    const float* xb0 = (const float*)d_in[9];
    const float* xw1 = (const float*)d_in[10];
    const float* xb1 = (const float*)d_in[11];
    const float* xw2 = (const float*)d_in[12];
    const float* xb2 = (const float*)d_in[13];
    const float* xw3 = (const float*)d_in[14];
    const float* yw0 = (const float*)d_in[15];
    const float* yb0 = (const float*)d_in[16];
    const float* yw1 = (const float*)d_in[17];
    const float* yb1 = (const float*)d_in[18];
    const float* yw2 = (const float*)d_in[19];
    const float* yb2 = (const float*)d_in[20];
    const float* yw3 = (const float*)d_in[21];
    const float* fbias = (const float*)d_in[22];
    float* out = (float*)d_out;

    cudaFuncSetAttribute(gemm1_mma, cudaFuncAttributeMaxDynamicSharedMemorySize, G1_SMEM);
    cudaFuncSetAttribute(gemm2_mma, cudaFuncAttributeMaxDynamicSharedMemorySize, G2_SMEM);
    cudaFuncSetAttribute(toep_mma,  cudaFuncAttributeMaxDynamicSharedMemorySize, TW_SMEM);

    filter_kernel<<<128, 64>>>(freq, xw0, xb0, xw1, xb1, xw2, xb2, xw3,
                               yw0, yb0, yw1, yb1, yw2, yb2, yw3);
    xsplit_kernel<<<16384, 256>>>(x);
    dim3 tb(32, 8);
    tsplit_inw_kernel<<<dim3(24, 8), tb>>>(in_w);
    tsplit_outw_kernel<<<dim3(8, 8), tb>>>(out_w);

    dim3 g1(6, 512);
    gemm1_mma<<<g1, 256, G1_SMEM>>>(in_b);

    dwconv_kernel<<<8192, 32>>>(sf_w, sf_b);
    toep_mma<<<1024, 256, TW_SMEM>>>(fbias);

    dim3 g2(2, 128, 4);
    gemm2_mma<<<g2, 256, G2_SMEM>>>(out_b, out);
}

// round 11
// speedup vs baseline: 1.3503x; 1.3503x over previous
#include <cuda_runtime.h>
#include <cuda_bf16.h>
#include <cstdint>
#include <math.h>

// ---------------------------------------------------------------------------
// HyenaOperator2d:  B=4, S=128, D=256, d3=768, L=16384, FO=64
// Tensor-core mma.sync bf16 hi/lo split (3 MMAs per fp32 product).
// Round-9 structure + pre-split x (gemm1 A staging = pure uint4 copies).
// ---------------------------------------------------------------------------

#define PI_F 3.14159265358979f
#define MIN_D (-3.0701134573253943f)
#define MAX_D (-15.350567286626972f)

__device__ float g_hxT[256 * 128];            // [d][s], includes *dec*(1/256)
__device__ float g_hyT[256 * 128];            // [d][s], includes *dec
__device__ float g_U [50331648];              // (b,768,16384) planar
__device__ float g_x0[16777216];              // (b,256,16384) planar
__device__ float g_vg[16777216];
__device__ float g_g [16777216];              // toep output, planar (b,d,l)

__device__ __nv_bfloat16 g_xhi[65536 * 256];      // x split, row-major [m][k]
__device__ __nv_bfloat16 g_xlo[65536 * 256];
__device__ __nv_bfloat16 g_inwT_hi [768 * 256];   // [n][k]
__device__ __nv_bfloat16 g_inwT_lo [768 * 256];
__device__ __nv_bfloat16 g_outwT_hi[256 * 256];   // [n][k]
__device__ __nv_bfloat16 g_outwT_lo[256 * 256];

// ---- helpers ---------------------------------------------------------------
__device__ __forceinline__ uint32_t smem_u32(const void* p) {
    uint32_t a;
    asm("{ .reg .u64 t; cvta.to.shared.u64 t, %1; cvt.u32.u64 %0, t; }"
        : "=r"(a) : "l"(p));
    return a;
}
__device__ __forceinline__ void split_bf16(float v, unsigned short& hi, unsigned short& lo) {
    __nv_bfloat16 h = __float2bfloat16(v);
    __nv_bfloat16 l = __float2bfloat16(v - __bfloat162float(h));
    hi = __bfloat16_as_ushort(h);
    lo = __bfloat16_as_ushort(l);
}
__device__ __forceinline__ void split4(float4 v, uint2& hv, uint2& lv) {
    unsigned short h0,h1,h2,h3,l0,l1,l2,l3;
    split_bf16(v.x, h0, l0); split_bf16(v.y, h1, l1);
    split_bf16(v.z, h2, l2); split_bf16(v.w, h3, l3);
    hv.x = ((uint32_t)h1 << 16) | h0;  hv.y = ((uint32_t)h3 << 16) | h2;
    lv.x = ((uint32_t)l1 << 16) | l0;  lv.y = ((uint32_t)l3 << 16) | l2;
}
__device__ __forceinline__ void ldsm4(uint32_t* r, uint32_t addr) {
    asm volatile("ldmatrix.sync.aligned.m8n8.x4.shared.b16 {%0,%1,%2,%3}, [%4];"
        : "=r"(r[0]), "=r"(r[1]), "=r"(r[2]), "=r"(r[3]) : "r"(addr));
}
__device__ __forceinline__ void mma_bf16(float* d, const uint32_t* a, const uint32_t* b) {
    asm volatile(
        "mma.sync.aligned.m16n8k16.row.col.f32.bf16.bf16.f32 "
        "{%0,%1,%2,%3}, {%4,%5,%6,%7}, {%8,%9}, {%0,%1,%2,%3};"
        : "+f"(d[0]), "+f"(d[1]), "+f"(d[2]), "+f"(d[3])
        : "r"(a[0]), "r"(a[1]), "r"(a[2]), "r"(a[3]), "r"(b[0]), "r"(b[1]));
}

// Warp-tile 64x32 split-bf16 MMA over staged K panel (nk16 steps of k=16).
template <int AST, int BST>
__device__ __forceinline__ void mma_panel(
    float acc[4][4][4],
    uint32_t ah, uint32_t al, uint32_t bh, uint32_t bl,
    int lane, int nk16)
{
    const int sub = lane >> 3, r = lane & 7;
    const int am = (sub & 1) * 8 + r;
    const int ak = (sub >> 1) * 8;
    const int bn = (sub >> 1) * 8 + r;
    const int bk = (sub & 1) * 8;
    for (int ks = 0; ks < nk16; ks++) {
        uint32_t AH[4][4], AL[4][4], BH[4][2], BL[4][2];
        #pragma unroll
        for (int mt = 0; mt < 4; mt++) {
            uint32_t off = (uint32_t)((mt * 16 + am) * AST + (ks * 16 + ak) * 2);
            ldsm4(AH[mt], ah + off);
            ldsm4(AL[mt], al + off);
        }
        #pragma unroll
        for (int np = 0; np < 2; np++) {
            uint32_t u[4];
            uint32_t off = (uint32_t)((np * 16 + bn) * BST + (ks * 16 + bk) * 2);
            ldsm4(u, bh + off);
            BH[2*np][0] = u[0]; BH[2*np][1] = u[1];
            BH[2*np+1][0] = u[2]; BH[2*np+1][1] = u[3];
            ldsm4(u, bl + off);
            BL[2*np][0] = u[0]; BL[2*np][1] = u[1];
            BL[2*np+1][0] = u[2]; BL[2*np+1][1] = u[3];
        }
        #pragma unroll
        for (int mt = 0; mt < 4; mt++)
            #pragma unroll
            for (int nt = 0; nt < 4; nt++) {
                mma_bf16(acc[mt][nt], AH[mt], BH[nt]);
                mma_bf16(acc[mt][nt], AH[mt], BL[nt]);
                mma_bf16(acc[mt][nt], AL[mt], BH[nt]);
            }
    }
}

// ---------------------------------------------------------------------------
// Implicit filter MLPs + positional embedding + decay. 128 blocks (s), 64 thr.
// ---------------------------------------------------------------------------
__global__ void filter_kernel(
    const float* __restrict__ freq,
    const float* __restrict__ xw0, const float* __restrict__ xb0,
    const float* __restrict__ xw1, const float* __restrict__ xb1,
    const float* __restrict__ xw2, const float* __restrict__ xb2,
    const float* __restrict__ xw3,
    const float* __restrict__ yw0, const float* __restrict__ yb0,
    const float* __restrict__ yw1, const float* __restrict__ yb1,
    const float* __restrict__ yw2, const float* __restrict__ yb2,
    const float* __restrict__ yw3)
{
    __shared__ float h[64];
    const int s = blockIdx.x;
    const int j = threadIdx.x;

    const float t   = (float)s / 127.0f;
    const float phi = 1e-4f * 2.0f * PI_F * (float)s / 128.0f;
    const float z0 = t, z1 = cosf(phi), z2 = -sinf(phi);
    const float fr = freq[j];

    for (int which = 0; which < 2; which++) {
        const float* w0 = which ? yw0 : xw0;  const float* b0 = which ? yb0 : xb0;
        const float* w1 = which ? yw1 : xw1;  const float* b1 = which ? yb1 : xb1;
        const float* w2 = which ? yw2 : xw2;  const float* b2 = which ? yb2 : xb2;
        const float* w3 = which ? yw3 : xw3;

        float v = z0 * w0[j] + z1 * w0[64 + j] + z2 * w0[128 + j] + b0[j];
        h[j] = sinf(fr * v);
        __syncthreads();

        float a = b1[j];
        #pragma unroll 8
        for (int k = 0; k < 64; k++) a += h[k] * w1[k * 64 + j];
        __syncthreads();
        h[j] = sinf(fr * a);
        __syncthreads();

        a = b2[j];
        #pragma unroll 8
        for (int k = 0; k < 64; k++) a += h[k] * w2[k * 64 + j];
        __syncthreads();
        h[j] = sinf(fr * a);
        __syncthreads();

        float o[4] = {0.f, 0.f, 0.f, 0.f};
        #pragma unroll 8
        for (int k = 0; k < 64; k++) {
            float hv = h[k];
            #pragma unroll
            for (int r = 0; r < 4; r++) o[r] += hv * w3[k * 256 + j + 64 * r];
        }
        #pragma unroll
        for (int r = 0; r < 4; r++) {
            int d = j + 64 * r;
            float delta = MIN_D + (MAX_D - MIN_D) * ((float)d / 255.0f);
            float dec = expf(-t * fabsf(delta));
            if (which == 0)
                g_hxT[d * 128 + s] = o[r] * dec * (1.0f / 256.0f);
            else
                g_hyT[d * 128 + s] = o[r] * dec;
        }
        __syncthreads();
    }
}

// ---------------------------------------------------------------------------
// x -> bf16 hi/lo split (row-major).  grid 16384 x 256.
// ---------------------------------------------------------------------------
__global__ __launch_bounds__(256) void xsplit_kernel(const float* __restrict__ X)
{
    size_t i = (size_t)blockIdx.x * 256 + threadIdx.x;
    float4 v = *(const float4*)(X + i * 4);
    uint2 hv, lv;
    split4(v, hv, lv);
    *(uint2*)(g_xhi + i * 4) = hv;
    *(uint2*)(g_xlo + i * 4) = lv;
}

// ---------------------------------------------------------------------------
// Tiled transpose + bf16 hi/lo split for weights.
// ---------------------------------------------------------------------------
__device__ __forceinline__ void do_tsplit(
    const float* __restrict__ src, __nv_bfloat16* __restrict__ dhi,
    __nv_bfloat16* __restrict__ dlo, int rows, int cols)
{
    __shared__ float tile[32][33];
    const int c0 = blockIdx.x * 32, r0 = blockIdx.y * 32;
    const int tx = threadIdx.x, ty = threadIdx.y;
    #pragma unroll
    for (int i = 0; i < 4; i++)
        tile[ty + 8 * i][tx] = src[(size_t)(r0 + ty + 8 * i) * cols + c0 + tx];
    __syncthreads();
    #pragma unroll
    for (int i = 0; i < 4; i++) {
        float v = tile[tx][ty + 8 * i];
        unsigned short hi, lo;
        split_bf16(v, hi, lo);
        size_t o = (size_t)(c0 + ty + 8 * i) * rows + r0 + tx;
        dhi[o] = __ushort_as_bfloat16(hi);
        dlo[o] = __ushort_as_bfloat16(lo);
    }
}
__global__ void tsplit_inw_kernel(const float* __restrict__ w) {
    do_tsplit(w, g_inwT_hi, g_inwT_lo, 256, 768);
}
__global__ void tsplit_outw_kernel(const float* __restrict__ w) {
    do_tsplit(w, g_outwT_hi, g_outwT_lo, 256, 256);
}

// ---------------------------------------------------------------------------
// GEMM1: U(b,c,l) = x @ in_w + in_b.  M=65536 K=256 N=768.
// grid(6,512) n-fast; A and B both pre-split bf16 (pure uint4 staging).
// ---------------------------------------------------------------------------
#define G1_SMEM 66048

__global__ __launch_bounds__(256) void gemm1_mma(const float* __restrict__ bias)
{
    extern __shared__ __align__(16) char sm[];
    const uint32_t smb = smem_u32(sm);
    const int tid = threadIdx.x, lane = tid & 31, wid = tid >> 5;
    const int wm = wid & 1, wn = wid >> 1;
    const int m0 = blockIdx.y * 128, n0 = blockIdx.x * 128;

    float acc[4][4][4];
    #pragma unroll
    for (int a = 0; a < 4; a++)
        #pragma unroll
        for (int b = 0; b < 4; b++)
            #pragma unroll
            for (int c = 0; c < 4; c++) acc[a][b][c] = 0.f;

    for (int kt = 0; kt < 8; kt++) {
        const int k0 = kt * 32;
        __syncthreads();
        // A: pre-split x hi/lo (pure uint4 copies, 128 rows x 32 k)
        #pragma unroll
        for (int e = tid; e < 512; e += 256) {
            int r = e >> 2, q = e & 3;
            size_t ga = (size_t)(m0 + r) * 256 + k0 + q * 8;
            *(uint4*)(sm +         r * 80 + q * 16) = *(const uint4*)(g_xhi + ga);
            *(uint4*)(sm + 10240 + r * 80 + q * 16) = *(const uint4*)(g_xlo + ga);
        }
        // B: precomputed in_wT hi/lo
        #pragma unroll
        for (int e = tid; e < 512; e += 256) {
            int r = e >> 2, q = e & 3;
            size_t gb = (size_t)(n0 + r) * 256 + k0 + q * 8;
            *(uint4*)(sm + 20480 + r * 80 + q * 16) = *(const uint4*)(g_inwT_hi + gb);
            *(uint4*)(sm + 30720 + r * 80 + q * 16) = *(const uint4*)(g_inwT_lo + gb);
        }
        __syncthreads();
        mma_panel<80, 80>(acc, smb + wm * 64 * 80, smb + 10240 + wm * 64 * 80,
                          smb + 20480 + wn * 32 * 80, smb + 30720 + wn * 32 * 80,
                          lane, 2);
    }

    __syncthreads();
    float* stg = (float*)sm;
    #pragma unroll
    for (int mt = 0; mt < 4; mt++)
        #pragma unroll
        for (int nt = 0; nt < 4; nt++) {
            int m = wm * 64 + mt * 16 + (lane >> 2);
            int n = wn * 32 + nt * 8 + 2 * (lane & 3);
            stg[m * 129 + n]           = acc[mt][nt][0];
            stg[m * 129 + n + 1]       = acc[mt][nt][1];
            stg[(m + 8) * 129 + n]     = acc[mt][nt][2];
            stg[(m + 8) * 129 + n + 1] = acc[mt][nt][3];
        }
    __syncthreads();
    const int b = m0 >> 14;
    const int l0 = m0 & 16383;
    const int mloc = tid & 63;
    #pragma unroll
    for (int j = 0; j < 32; j++) {
        int n = j * 4 + (tid >> 6);
        float bb = __ldg(bias + n0 + n);
        float* dst = g_U + ((size_t)(b * 768 + n0 + n) << 14) + l0;
        dst[mloc]      = stg[mloc * 129 + n] + bb;
        dst[mloc + 64] = stg[(mloc + 64) * 129 + n] + bb;
    }
}

// ---------------------------------------------------------------------------
// GEMM2: out(b,l,n) = g(b,d,l)^T @ out_wT + out_b.  grid(2,128,4) n-fast.
// ---------------------------------------------------------------------------
#define G2_SMEM 40960

__global__ __launch_bounds__(256) void gemm2_mma(
    const float* __restrict__ bias, float* __restrict__ Out)
{
    extern __shared__ __align__(16) char sm[];
    const uint32_t smb = smem_u32(sm);
    const int tid = threadIdx.x, lane = tid & 31, wid = tid >> 5;
    const int wm = wid & 1, wn = wid >> 1;
    const int m0 = blockIdx.y * 128, n0 = blockIdx.x * 128;
    const int b = blockIdx.z;
    const float* Gb = g_g + ((size_t)b << 22);

    float acc[4][4][4];
    #pragma unroll
    for (int a = 0; a < 4; a++)
        #pragma unroll
        for (int c = 0; c < 4; c++)
            #pragma unroll
            for (int e = 0; e < 4; e++) acc[a][c][e] = 0.f;

    for (int kt = 0; kt < 8; kt++) {
        const int k0 = kt * 32;
        __syncthreads();
        // A: transpose+split from planar g: A[m=l][k=d]
        #pragma unroll
        for (int e = tid; e < 1024; e += 256) {
            int lloc = e & 127, dq = e >> 7;
            unsigned short h[4], l[4];
            #pragma unroll
            for (int t = 0; t < 4; t++) {
                float v = Gb[((size_t)(k0 + dq * 4 + t) << 14) + m0 + lloc];
                split_bf16(v, h[t], l[t]);
            }
            uint2 hv, lv;
            hv.x = ((uint32_t)h[1] << 16) | h[0];  hv.y = ((uint32_t)h[3] << 16) | h[2];
            lv.x = ((uint32_t)l[1] << 16) | l[0];  lv.y = ((uint32_t)l[3] << 16) | l[2];
            *(uint2*)(sm +         lloc * 80 + dq * 8) = hv;
            *(uint2*)(sm + 10240 + lloc * 80 + dq * 8) = lv;
        }
        // B: precomputed out_wT hi/lo
        #pragma unroll
        for (int e = tid; e < 512; e += 256) {
            int r = e >> 2, q = e & 3;
            size_t gb = (size_t)(n0 + r) * 256 + k0 + q * 8;
            *(uint4*)(sm + 20480 + r * 80 + q * 16) = *(const uint4*)(g_outwT_hi + gb);
            *(uint4*)(sm + 30720 + r * 80 + q * 16) = *(const uint4*)(g_outwT_lo + gb);
        }
        __syncthreads();
        mma_panel<80, 80>(acc, smb + wm * 64 * 80, smb + 10240 + wm * 64 * 80,
                          smb + 20480 + wn * 32 * 80, smb + 30720 + wn * 32 * 80,
                          lane, 2);
    }

    #pragma unroll
    for (int mt = 0; mt < 4; mt++)
        #pragma unroll
        for (int nt = 0; nt < 4; nt++) {
            int m = m0 + wm * 64 + mt * 16 + (lane >> 2);
            int n = n0 + wn * 32 + nt * 8 + 2 * (lane & 3);
            float2 bb = *(const float2*)&bias[n];
            float2 v0 = { acc[mt][nt][0] + bb.x, acc[mt][nt][1] + bb.y };
            float2 v1 = { acc[mt][nt][2] + bb.x, acc[mt][nt][3] + bb.y };
            *(float2*)&Out[(((size_t)b << 14) + m) * 256 + n] = v0;
            *(float2*)&Out[(((size_t)b << 14) + m + 8) * 256 + n] = v1;
        }
}

// ---------------------------------------------------------------------------
// Depthwise 3x3 conv, float4 + shfl. grid 2048 x 32 threads (round-9 form).
// ---------------------------------------------------------------------------
__device__ __forceinline__ float4 hconv(float4 c, float m1, float m2,
                                        float w0, float w1, float w2) {
    float4 o;
    o.x = w0 * m2  + w1 * m1  + w2 * c.x;
    o.y = w0 * m1  + w1 * c.x + w2 * c.y;
    o.z = w0 * c.x + w1 * c.y + w2 * c.z;
    o.w = w0 * c.y + w1 * c.z + w2 * c.w;
    return o;
}
__device__ __forceinline__ void lnbr(float4 c, int lane, float& m1, float& m2) {
    m1 = __shfl_up_sync(0xFFFFFFFFu, c.w, 1);
    m2 = __shfl_up_sync(0xFFFFFFFFu, c.z, 1);
    if (lane == 0) { m1 = 0.f; m2 = 0.f; }
}

__global__ __launch_bounds__(32) void dwconv_kernel(
    const float* __restrict__ sfw, const float* __restrict__ sfb)
{
    const int bd = blockIdx.x >> 1;
    const int which = blockIdx.x & 1;
    const int b = bd >> 8, d = bd & 255;
    const int lane = threadIdx.x;
    const size_t outp = (size_t)bd << 14;

    if (which == 0) {
        const float* p = g_U + ((size_t)(b * 768 + d) << 14);
        float w[9];
        #pragma unroll
        for (int q = 0; q < 9; q++) w[q] = sfw[d * 9 + q];
        const float bs = sfb[d];
        float4 av = {0,0,0,0}, rv = {0,0,0,0};
        float am1 = 0, am2 = 0, rm1 = 0, rm2 = 0;
        for (int i = 0; i < 128; i++) {
            float4 cv = *(const float4*)(p + i * 128 + lane * 4);
            float cm1, cm2;
            lnbr(cv, lane, cm1, cm2);
            float4 o = hconv(av, am1, am2, w[0], w[1], w[2]);
            float4 o2 = hconv(rv, rm1, rm2, w[3], w[4], w[5]);
            float4 o3 = hconv(cv, cm1, cm2, w[6], w[7], w[8]);
            float4 r;
            r.x = bs + o.x + o2.x + o3.x;
            r.y = bs + o.y + o2.y + o3.y;
            r.z = bs + o.z + o2.z + o3.z;
            r.w = bs + o.w + o2.w + o3.w;
            *(float4*)(g_x0 + outp + i * 128 + lane * 4) = r;
            av = rv; am1 = rm1; am2 = rm2;
            rv = cv; rm1 = cm1; rm2 = cm2;
        }
    } else {
        const float* p1 = g_U + ((size_t)(b * 768 + 256 + d) << 14);
        const float* p2 = g_U + ((size_t)(b * 768 + 512 + d) << 14);
        float w1[9], w2[9];
        #pragma unroll
        for (int q = 0; q < 9; q++) {
            w1[q] = sfw[(256 + d) * 9 + q];
            w2[q] = sfw[(512 + d) * 9 + q];
        }
        const float bs1 = sfb[256 + d], bs2 = sfb[512 + d];
        float4 av1 = {0,0,0,0}, rv1 = {0,0,0,0}, av2 = {0,0,0,0}, rv2 = {0,0,0,0};
        float am11=0, am12=0, rm11=0, rm12=0, am21=0, am22=0, rm21=0, rm22=0;
        for (int i = 0; i < 128; i++) {
            float4 cv1 = *(const float4*)(p1 + i * 128 + lane * 4);
            float4 cv2 = *(const float4*)(p2 + i * 128 + lane * 4);
            float cm11, cm12, cm21, cm22;
            lnbr(cv1, lane, cm11, cm12);
            lnbr(cv2, lane, cm21, cm22);
            float4 oa = hconv(av1, am11, am12, w1[0], w1[1], w1[2]);
            float4 ob = hconv(rv1, rm11, rm12, w1[3], w1[4], w1[5]);
            float4 oc = hconv(cv1, cm11, cm12, w1[6], w1[7], w1[8]);
            float4 pa = hconv(av2, am21, am22, w2[0], w2[1], w2[2]);
            float4 pb = hconv(rv2, rm21, rm22, w2[3], w2[4], w2[5]);
            float4 pc = hconv(cv2, cm21, cm22, w2[6], w2[7], w2[8]);
            float4 r;
            r.x = (bs1 + oa.x + ob.x + oc.x) * (bs2 + pa.x + pb.x + pc.x);
            r.y = (bs1 + oa.y + ob.y + oc.y) * (bs2 + pa.y + pb.y + pc.y);
            r.z = (bs1 + oa.z + ob.z + oc.z) * (bs2 + pa.z + pb.z + pc.z);
            r.w = (bs1 + oa.w + ob.w + oc.w) * (bs2 + pa.w + pb.w + pc.w);
            *(float4*)(g_vg + outp + i * 128 + lane * 4) = r;
            av1 = rv1; am11 = rm11; am12 = rm12;
            rv1 = cv1; rm11 = cm11; rm12 = cm12;
            av2 = rv2; am21 = rm21; am22 = rm22;
            rv2 = cv2; rm21 = cm21; rm22 = cm22;
        }
    }
}

// ---------------------------------------------------------------------------
// Fused Toeplitz, 2 CTAs/SM (109KB smem). Chunked staging, persistent W1.
// ---------------------------------------------------------------------------
#define TW_W1H 0
#define TW_W1L 34816
#define TW_AH  69632
#define TW_AL  79872
#define TW_BH  90112
#define TW_BL  100352
#define TW_HV  110592
#define TW_SMEM 111616

__global__ __launch_bounds__(256) void toep_mma(const float* __restrict__ fbias)
{
    extern __shared__ __align__(16) char sm[];
    const uint32_t smb = smem_u32(sm);
    float* hxs = (float*)(sm + TW_HV);
    float* hys = hxs + 128;
    const int tid = threadIdx.x, lane = tid & 31, wid = tid >> 5;
    const int wm = wid & 1, wn = wid >> 1;
    const int bd = blockIdx.x;
    const int d = bd & 255;
    const float* vgp = g_vg + ((size_t)bd << 14);
    const int aq = tid & 7, ar0 = tid >> 3;

    if (tid < 128) {
        hxs[tid] = g_hxT[d * 128 + tid];
        hys[tid] = g_hyT[d * 128 + tid];
    }
    __syncthreads();

    float acc[4][4][4];
    #pragma unroll
    for (int a = 0; a < 4; a++)
        #pragma unroll
        for (int b = 0; b < 4; b++)
            #pragma unroll
            for (int c = 0; c < 4; c++) acc[a][b][c] = 0.f;

    // ---- pass 1: W1 = VG @ T(hy), 4 chunks of k=32 ----
    for (int kc = 0; kc < 4; kc++) {
        if (kc > 0) __syncthreads();
        #pragma unroll
        for (int i = 0; i < 4; i++) {
            int r = ar0 + 32 * i;
            int c = kc * 32 + aq * 4;
            float4 v = *(const float4*)(vgp + r * 128 + c);
            uint2 hv, lv;
            split4(v, hv, lv);
            *(uint2*)(sm + TW_AH + r * 80 + aq * 8) = hv;
            *(uint2*)(sm + TW_AL + r * 80 + aq * 8) = lv;
            float4 t;
            t.x = (r - c     >= 0) ? hys[r - c]     : 0.f;
            t.y = (r - c - 1 >= 0) ? hys[r - c - 1] : 0.f;
            t.z = (r - c - 2 >= 0) ? hys[r - c - 2] : 0.f;
            t.w = (r - c - 3 >= 0) ? hys[r - c - 3] : 0.f;
            split4(t, hv, lv);
            *(uint2*)(sm + TW_BH + r * 80 + aq * 8) = hv;
            *(uint2*)(sm + TW_BL + r * 80 + aq * 8) = lv;
        }
        __syncthreads();
        mma_panel<80, 80>(acc,
            smb + TW_AH + wm * 64 * 80, smb + TW_AL + wm * 64 * 80,
            smb + TW_BH + wn * 32 * 80, smb + TW_BL + wn * 32 * 80, lane, 2);
    }
    __syncthreads();

    // W1^T split -> persistent W1 region (stride 136)
    __nv_bfloat16* bh = (__nv_bfloat16*)(sm + TW_W1H);
    __nv_bfloat16* bl = (__nv_bfloat16*)(sm + TW_W1L);
    #pragma unroll
    for (int mt = 0; mt < 4; mt++)
        #pragma unroll
        for (int nt = 0; nt < 4; nt++) {
            int m = wm * 64 + mt * 16 + (lane >> 2);
            int n = wn * 32 + nt * 8 + 2 * (lane & 3);
            unsigned short h, l;
            split_bf16(acc[mt][nt][0], h, l);
            bh[n * 136 + m] = __ushort_as_bfloat16(h);
            bl[n * 136 + m] = __ushort_as_bfloat16(l);
            split_bf16(acc[mt][nt][1], h, l);
            bh[(n + 1) * 136 + m] = __ushort_as_bfloat16(h);
            bl[(n + 1) * 136 + m] = __ushort_as_bfloat16(l);
            split_bf16(acc[mt][nt][2], h, l);
            bh[n * 136 + m + 8] = __ushort_as_bfloat16(h);
            bl[n * 136 + m + 8] = __ushort_as_bfloat16(l);
            split_bf16(acc[mt][nt][3], h, l);
            bh[(n + 1) * 136 + m + 8] = __ushort_as_bfloat16(h);
            bl[(n + 1) * 136 + m + 8] = __ushort_as_bfloat16(l);
            acc[mt][nt][0] = acc[mt][nt][1] = acc[mt][nt][2] = acc[mt][nt][3] = 0.f;
        }

    // ---- pass 2: C = T(hx) @ W1 ----
    for (int kc = 0; kc < 4; kc++) {
        __syncthreads();
        #pragma unroll
        for (int i = 0; i < 4; i++) {
            int r = ar0 + 32 * i;
            int c = kc * 32 + aq * 4;
            float4 t;
            t.x = (r - c     >= 0) ? hxs[r - c]     : 0.f;
            t.y = (r - c - 1 >= 0) ? hxs[r - c - 1] : 0.f;
            t.z = (r - c - 2 >= 0) ? hxs[r - c - 2] : 0.f;
            t.w = (r - c - 3 >= 0) ? hxs[r - c - 3] : 0.f;
            uint2 hv, lv;
            split4(t, hv, lv);
            *(uint2*)(sm + TW_AH + r * 80 + aq * 8) = hv;
            *(uint2*)(sm + TW_AL + r * 80 + aq * 8) = lv;
        }
        __syncthreads();
        mma_panel<80, 272>(acc,
            smb + TW_AH + wm * 64 * 80, smb + TW_AL + wm * 64 * 80,
            smb + TW_W1H + wn * 32 * 272 + kc * 64,
            smb + TW_W1L + wn * 32 * 272 + kc * 64, lane, 2);
    }

    // epilogue: g = (C + vg*fb) * x0
    const float fb = fbias[d];
    const float* x0p = g_x0 + ((size_t)bd << 14);
    float* gp = g_g + ((size_t)bd << 14);
    #pragma unroll
    for (int mt = 0; mt < 4; mt++)
        #pragma unroll
        for (int nt = 0; nt < 4; nt++) {
            int m = wm * 64 + mt * 16 + (lane >> 2);
            int n = wn * 32 + nt * 8 + 2 * (lane & 3);
            #pragma unroll
            for (int half = 0; half < 2; half++) {
                int idx = (m + 8 * half) * 128 + n;
                float2 c = { acc[mt][nt][2 * half], acc[mt][nt][2 * half + 1] };
                float2 v = *(const float2*)(vgp + idx);
                float2 x = *(const float2*)(x0p + idx);
                float2 r;
                r.x = (c.x + v.x * fb) * x.x;
                r.y = (c.y + v.y * fb) * x.y;
                *(float2*)(gp + idx) = r;
            }
        }
}

// ---------------------------------------------------------------------------
extern "C" void kernel_launch(void* const* d_in, const int* in_sizes, int n_in,
                              void* d_out, int out_size)
{
    (void)in_sizes; (void)n_in; (void)out_size;
    const float* x     = (const float*)d_in[0];
    const float* in_w  = (const float*)d_in[1];
    const float* in_b  = (const float*)d_in[2];
    const float* out_w = (const float*)d_in[3];
    const float* out_b = (const float*)d_in[4];
    const float* sf_w  = (const float*)d_in[5];
    const float* sf_b  = (const float*)d_in[6];
    const float* freq  = (const float*)d_in[7];
    const float* xw0 = (const float*)d_in[8];
    const float* xb0 = (const float*)d_in[9];
    const float* xw1 = (const float*)d_in[10];
    const float* xb1 = (const float*)d_in[11];
    const float* xw2 = (const float*)d_in[12];
    const float* xb2 = (const float*)d_in[13];
    const float* xw3 = (const float*)d_in[14];
    const float* yw0 = (const float*)d_in[15];
    const float* yb0 = (const float*)d_in[16];
    const float* yw1 = (const float*)d_in[17];
    const float* yb1 = (const float*)d_in[18];
    const float* yw2 = (const float*)d_in[19];
    const float* yb2 = (const float*)d_in[20];
    const float* yw3 = (const float*)d_in[21];
    const float* fbias = (const float*)d_in[22];
    float* out = (float*)d_out;

    cudaFuncSetAttribute(gemm1_mma, cudaFuncAttributeMaxDynamicSharedMemorySize, G1_SMEM);
    cudaFuncSetAttribute(gemm2_mma, cudaFuncAttributeMaxDynamicSharedMemorySize, G2_SMEM);
    cudaFuncSetAttribute(toep_mma,  cudaFuncAttributeMaxDynamicSharedMemorySize, TW_SMEM);

    filter_kernel<<<128, 64>>>(freq, xw0, xb0, xw1, xb1, xw2, xb2, xw3,
                               yw0, yb0, yw1, yb1, yw2, yb2, yw3);
    xsplit_kernel<<<16384, 256>>>(x);
    dim3 tb(32, 8);
    tsplit_inw_kernel<<<dim3(24, 8), tb>>>(in_w);
    tsplit_outw_kernel<<<dim3(8, 8), tb>>>(out_w);

    dim3 g1(6, 512);
    gemm1_mma<<<g1, 256, G1_SMEM>>>(in_b);

    dwconv_kernel<<<2048, 32>>>(sf_w, sf_b);
    toep_mma<<<1024, 256, TW_SMEM>>>(fbias);

    dim3 g2(2, 128, 4);
    gemm2_mma<<<g2, 256, G2_SMEM>>>(out_b, out);
}

// round 12
// speedup vs baseline: 1.5346x; 1.1365x over previous
#include <cuda_runtime.h>
#include <cuda_bf16.h>
#include <cstdint>
#include <math.h>

// ---------------------------------------------------------------------------
// HyenaOperator2d:  B=4, S=128, D=256, d3=768, L=16384, FO=64
// Tensor-core mma.sync bf16 hi/lo split (3 MMAs per fp32 product).
// Round-9 structure (known best) + row-chunked dwconv.
// ---------------------------------------------------------------------------

#define PI_F 3.14159265358979f
#define MIN_D (-3.0701134573253943f)
#define MAX_D (-15.350567286626972f)

__device__ float g_hxT[256 * 128];            // [d][s], includes *dec*(1/256)
__device__ float g_hyT[256 * 128];            // [d][s], includes *dec
__device__ float g_U [50331648];              // (b,768,16384) planar
__device__ float g_x0[16777216];              // (b,256,16384) planar
__device__ float g_vg[16777216];
__device__ float g_g [16777216];              // toep output, planar (b,d,l)

__device__ __nv_bfloat16 g_inwT_hi [768 * 256];   // [n][k]
__device__ __nv_bfloat16 g_inwT_lo [768 * 256];
__device__ __nv_bfloat16 g_outwT_hi[256 * 256];   // [n][k]
__device__ __nv_bfloat16 g_outwT_lo[256 * 256];

// ---- helpers ---------------------------------------------------------------
__device__ __forceinline__ uint32_t smem_u32(const void* p) {
    uint32_t a;
    asm("{ .reg .u64 t; cvta.to.shared.u64 t, %1; cvt.u32.u64 %0, t; }"
        : "=r"(a) : "l"(p));
    return a;
}
__device__ __forceinline__ void split_bf16(float v, unsigned short& hi, unsigned short& lo) {
    __nv_bfloat16 h = __float2bfloat16(v);
    __nv_bfloat16 l = __float2bfloat16(v - __bfloat162float(h));
    hi = __bfloat16_as_ushort(h);
    lo = __bfloat16_as_ushort(l);
}
__device__ __forceinline__ void split4(float4 v, uint2& hv, uint2& lv) {
    unsigned short h0,h1,h2,h3,l0,l1,l2,l3;
    split_bf16(v.x, h0, l0); split_bf16(v.y, h1, l1);
    split_bf16(v.z, h2, l2); split_bf16(v.w, h3, l3);
    hv.x = ((uint32_t)h1 << 16) | h0;  hv.y = ((uint32_t)h3 << 16) | h2;
    lv.x = ((uint32_t)l1 << 16) | l0;  lv.y = ((uint32_t)l3 << 16) | l2;
}
__device__ __forceinline__ void ldsm4(uint32_t* r, uint32_t addr) {
    asm volatile("ldmatrix.sync.aligned.m8n8.x4.shared.b16 {%0,%1,%2,%3}, [%4];"
        : "=r"(r[0]), "=r"(r[1]), "=r"(r[2]), "=r"(r[3]) : "r"(addr));
}
__device__ __forceinline__ void mma_bf16(float* d, const uint32_t* a, const uint32_t* b) {
    asm volatile(
        "mma.sync.aligned.m16n8k16.row.col.f32.bf16.bf16.f32 "
        "{%0,%1,%2,%3}, {%4,%5,%6,%7}, {%8,%9}, {%0,%1,%2,%3};"
        : "+f"(d[0]), "+f"(d[1]), "+f"(d[2]), "+f"(d[3])
        : "r"(a[0]), "r"(a[1]), "r"(a[2]), "r"(a[3]), "r"(b[0]), "r"(b[1]));
}

// Warp-tile 64x32 split-bf16 MMA over staged K panel (nk16 steps of k=16).
template <int AST, int BST>
__device__ __forceinline__ void mma_panel(
    float acc[4][4][4],
    uint32_t ah, uint32_t al, uint32_t bh, uint32_t bl,
    int lane, int nk16)
{
    const int sub = lane >> 3, r = lane & 7;
    const int am = (sub & 1) * 8 + r;
    const int ak = (sub >> 1) * 8;
    const int bn = (sub >> 1) * 8 + r;
    const int bk = (sub & 1) * 8;
    for (int ks = 0; ks < nk16; ks++) {
        uint32_t AH[4][4], AL[4][4], BH[4][2], BL[4][2];
        #pragma unroll
        for (int mt = 0; mt < 4; mt++) {
            uint32_t off = (uint32_t)((mt * 16 + am) * AST + (ks * 16 + ak) * 2);
            ldsm4(AH[mt], ah + off);
            ldsm4(AL[mt], al + off);
        }
        #pragma unroll
        for (int np = 0; np < 2; np++) {
            uint32_t u[4];
            uint32_t off = (uint32_t)((np * 16 + bn) * BST + (ks * 16 + bk) * 2);
            ldsm4(u, bh + off);
            BH[2*np][0] = u[0]; BH[2*np][1] = u[1];
            BH[2*np+1][0] = u[2]; BH[2*np+1][1] = u[3];
            ldsm4(u, bl + off);
            BL[2*np][0] = u[0]; BL[2*np][1] = u[1];
            BL[2*np+1][0] = u[2]; BL[2*np+1][1] = u[3];
        }
        #pragma unroll
        for (int mt = 0; mt < 4; mt++)
            #pragma unroll
            for (int nt = 0; nt < 4; nt++) {
                mma_bf16(acc[mt][nt], AH[mt], BH[nt]);
                mma_bf16(acc[mt][nt], AH[mt], BL[nt]);
                mma_bf16(acc[mt][nt], AL[mt], BH[nt]);
            }
    }
}

// ---------------------------------------------------------------------------
// Implicit filter MLPs + positional embedding + decay. 128 blocks (s), 64 thr.
// ---------------------------------------------------------------------------
__global__ void filter_kernel(
    const float* __restrict__ freq,
    const float* __restrict__ xw0, const float* __restrict__ xb0,
    const float* __restrict__ xw1, const float* __restrict__ xb1,
    const float* __restrict__ xw2, const float* __restrict__ xb2,
    const float* __restrict__ xw3,
    const float* __restrict__ yw0, const float* __restrict__ yb0,
    const float* __restrict__ yw1, const float* __restrict__ yb1,
    const float* __restrict__ yw2, const float* __restrict__ yb2,
    const float* __restrict__ yw3)
{
    __shared__ float h[64];
    const int s = blockIdx.x;
    const int j = threadIdx.x;

    const float t   = (float)s / 127.0f;
    const float phi = 1e-4f * 2.0f * PI_F * (float)s / 128.0f;
    const float z0 = t, z1 = cosf(phi), z2 = -sinf(phi);
    const float fr = freq[j];

    for (int which = 0; which < 2; which++) {
        const float* w0 = which ? yw0 : xw0;  const float* b0 = which ? yb0 : xb0;
        const float* w1 = which ? yw1 : xw1;  const float* b1 = which ? yb1 : xb1;
        const float* w2 = which ? yw2 : xw2;  const float* b2 = which ? yb2 : xb2;
        const float* w3 = which ? yw3 : xw3;

        float v = z0 * w0[j] + z1 * w0[64 + j] + z2 * w0[128 + j] + b0[j];
        h[j] = sinf(fr * v);
        __syncthreads();

        float a = b1[j];
        #pragma unroll 8
        for (int k = 0; k < 64; k++) a += h[k] * w1[k * 64 + j];
        __syncthreads();
        h[j] = sinf(fr * a);
        __syncthreads();

        a = b2[j];
        #pragma unroll 8
        for (int k = 0; k < 64; k++) a += h[k] * w2[k * 64 + j];
        __syncthreads();
        h[j] = sinf(fr * a);
        __syncthreads();

        float o[4] = {0.f, 0.f, 0.f, 0.f};
        #pragma unroll 8
        for (int k = 0; k < 64; k++) {
            float hv = h[k];
            #pragma unroll
            for (int r = 0; r < 4; r++) o[r] += hv * w3[k * 256 + j + 64 * r];
        }
        #pragma unroll
        for (int r = 0; r < 4; r++) {
            int d = j + 64 * r;
            float delta = MIN_D + (MAX_D - MIN_D) * ((float)d / 255.0f);
            float dec = expf(-t * fabsf(delta));
            if (which == 0)
                g_hxT[d * 128 + s] = o[r] * dec * (1.0f / 256.0f);
            else
                g_hyT[d * 128 + s] = o[r] * dec;
        }
        __syncthreads();
    }
}

// ---------------------------------------------------------------------------
// Tiled transpose + bf16 hi/lo split for both weights in one launch.
// grid.x 0..23 -> in_w (768 cols); grid.x 24..31 -> out_w (256 cols).
// ---------------------------------------------------------------------------
__device__ __forceinline__ void do_tsplit(
    const float* __restrict__ src, __nv_bfloat16* __restrict__ dhi,
    __nv_bfloat16* __restrict__ dlo, int rows, int cols, int bx)
{
    __shared__ float tile[32][33];
    const int c0 = bx * 32, r0 = blockIdx.y * 32;
    const int tx = threadIdx.x, ty = threadIdx.y;
    #pragma unroll
    for (int i = 0; i < 4; i++)
        tile[ty + 8 * i][tx] = src[(size_t)(r0 + ty + 8 * i) * cols + c0 + tx];
    __syncthreads();
    #pragma unroll
    for (int i = 0; i < 4; i++) {
        float v = tile[tx][ty + 8 * i];
        unsigned short hi, lo;
        split_bf16(v, hi, lo);
        size_t o = (size_t)(c0 + ty + 8 * i) * rows + r0 + tx;
        dhi[o] = __ushort_as_bfloat16(hi);
        dlo[o] = __ushort_as_bfloat16(lo);
    }
}
__global__ void tsplit_kernel(const float* __restrict__ inw,
                              const float* __restrict__ outw) {
    if (blockIdx.x < 24)
        do_tsplit(inw, g_inwT_hi, g_inwT_lo, 256, 768, blockIdx.x);
    else
        do_tsplit(outw, g_outwT_hi, g_outwT_lo, 256, 256, blockIdx.x - 24);
}

// ---------------------------------------------------------------------------
// GEMM1: U(b,c,l) = x @ in_w + in_b.  M=65536 K=256 N=768.
// grid(6,512) n-fast; inline A split (round-9 measured-best form).
// ---------------------------------------------------------------------------
#define G1_SMEM 66048

__global__ __launch_bounds__(256) void gemm1_mma(
    const float* __restrict__ X, const float* __restrict__ bias)
{
    extern __shared__ __align__(16) char sm[];
    const uint32_t smb = smem_u32(sm);
    const int tid = threadIdx.x, lane = tid & 31, wid = tid >> 5;
    const int wm = wid & 1, wn = wid >> 1;
    const int m0 = blockIdx.y * 128, n0 = blockIdx.x * 128;

    float acc[4][4][4];
    #pragma unroll
    for (int a = 0; a < 4; a++)
        #pragma unroll
        for (int b = 0; b < 4; b++)
            #pragma unroll
            for (int c = 0; c < 4; c++) acc[a][b][c] = 0.f;

    for (int kt = 0; kt < 8; kt++) {
        const int k0 = kt * 32;
        __syncthreads();
        // A: split x fp32 -> hi/lo (128 rows x 32 k)
        #pragma unroll
        for (int e = tid; e < 1024; e += 256) {
            int r = e >> 3, q = e & 7;
            float4 v = *(const float4*)(X + (size_t)(m0 + r) * 256 + k0 + q * 4);
            uint2 hv, lv;
            split4(v, hv, lv);
            *(uint2*)(sm +         r * 80 + q * 8) = hv;
            *(uint2*)(sm + 10240 + r * 80 + q * 8) = lv;
        }
        // B: precomputed in_wT hi/lo
        #pragma unroll
        for (int e = tid; e < 512; e += 256) {
            int r = e >> 2, q = e & 3;
            size_t gb = (size_t)(n0 + r) * 256 + k0 + q * 8;
            *(uint4*)(sm + 20480 + r * 80 + q * 16) = *(const uint4*)(g_inwT_hi + gb);
            *(uint4*)(sm + 30720 + r * 80 + q * 16) = *(const uint4*)(g_inwT_lo + gb);
        }
        __syncthreads();
        mma_panel<80, 80>(acc, smb + wm * 64 * 80, smb + 10240 + wm * 64 * 80,
                          smb + 20480 + wn * 32 * 80, smb + 30720 + wn * 32 * 80,
                          lane, 2);
    }

    __syncthreads();
    float* stg = (float*)sm;
    #pragma unroll
    for (int mt = 0; mt < 4; mt++)
        #pragma unroll
        for (int nt = 0; nt < 4; nt++) {
            int m = wm * 64 + mt * 16 + (lane >> 2);
            int n = wn * 32 + nt * 8 + 2 * (lane & 3);
            stg[m * 129 + n]           = acc[mt][nt][0];
            stg[m * 129 + n + 1]       = acc[mt][nt][1];
            stg[(m + 8) * 129 + n]     = acc[mt][nt][2];
            stg[(m + 8) * 129 + n + 1] = acc[mt][nt][3];
        }
    __syncthreads();
    const int b = m0 >> 14;
    const int l0 = m0 & 16383;
    const int mloc = tid & 63;
    #pragma unroll
    for (int j = 0; j < 32; j++) {
        int n = j * 4 + (tid >> 6);
        float bb = __ldg(bias + n0 + n);
        float* dst = g_U + ((size_t)(b * 768 + n0 + n) << 14) + l0;
        dst[mloc]      = stg[mloc * 129 + n] + bb;
        dst[mloc + 64] = stg[(mloc + 64) * 129 + n] + bb;
    }
}

// ---------------------------------------------------------------------------
// GEMM2: out(b,l,n) = g(b,d,l)^T @ out_wT + out_b.  grid(2,128,4) n-fast.
// ---------------------------------------------------------------------------
#define G2_SMEM 40960

__global__ __launch_bounds__(256) void gemm2_mma(
    const float* __restrict__ bias, float* __restrict__ Out)
{
    extern __shared__ __align__(16) char sm[];
    const uint32_t smb = smem_u32(sm);
    const int tid = threadIdx.x, lane = tid & 31, wid = tid >> 5;
    const int wm = wid & 1, wn = wid >> 1;
    const int m0 = blockIdx.y * 128, n0 = blockIdx.x * 128;
    const int b = blockIdx.z;
    const float* Gb = g_g + ((size_t)b << 22);

    float acc[4][4][4];
    #pragma unroll
    for (int a = 0; a < 4; a++)
        #pragma unroll
        for (int c = 0; c < 4; c++)
            #pragma unroll
            for (int e = 0; e < 4; e++) acc[a][c][e] = 0.f;

    for (int kt = 0; kt < 8; kt++) {
        const int k0 = kt * 32;
        __syncthreads();
        // A: transpose+split from planar g: A[m=l][k=d]
        #pragma unroll
        for (int e = tid; e < 1024; e += 256) {
            int lloc = e & 127, dq = e >> 7;
            unsigned short h[4], l[4];
            #pragma unroll
            for (int t = 0; t < 4; t++) {
                float v = Gb[((size_t)(k0 + dq * 4 + t) << 14) + m0 + lloc];
                split_bf16(v, h[t], l[t]);
            }
            uint2 hv, lv;
            hv.x = ((uint32_t)h[1] << 16) | h[0];  hv.y = ((uint32_t)h[3] << 16) | h[2];
            lv.x = ((uint32_t)l[1] << 16) | l[0];  lv.y = ((uint32_t)l[3] << 16) | l[2];
            *(uint2*)(sm +         lloc * 80 + dq * 8) = hv;
            *(uint2*)(sm + 10240 + lloc * 80 + dq * 8) = lv;
        }
        // B: precomputed out_wT hi/lo
        #pragma unroll
        for (int e = tid; e < 512; e += 256) {
            int r = e >> 2, q = e & 3;
            size_t gb = (size_t)(n0 + r) * 256 + k0 + q * 8;
            *(uint4*)(sm + 20480 + r * 80 + q * 16) = *(const uint4*)(g_outwT_hi + gb);
            *(uint4*)(sm + 30720 + r * 80 + q * 16) = *(const uint4*)(g_outwT_lo + gb);
        }
        __syncthreads();
        mma_panel<80, 80>(acc, smb + wm * 64 * 80, smb + 10240 + wm * 64 * 80,
                          smb + 20480 + wn * 32 * 80, smb + 30720 + wn * 32 * 80,
                          lane, 2);
    }

    #pragma unroll
    for (int mt = 0; mt < 4; mt++)
        #pragma unroll
        for (int nt = 0; nt < 4; nt++) {
            int m = m0 + wm * 64 + mt * 16 + (lane >> 2);
            int n = n0 + wn * 32 + nt * 8 + 2 * (lane & 3);
            float2 bb = *(const float2*)&bias[n];
            float2 v0 = { acc[mt][nt][0] + bb.x, acc[mt][nt][1] + bb.y };
            float2 v1 = { acc[mt][nt][2] + bb.x, acc[mt][nt][3] + bb.y };
            *(float2*)&Out[(((size_t)b << 14) + m) * 256 + n] = v0;
            *(float2*)&Out[(((size_t)b << 14) + m + 8) * 256 + n] = v1;
        }
}

// ---------------------------------------------------------------------------
// Depthwise 3x3 conv, float4 + shfl, 4 row-chunks per plane-task.
// grid 8192 x 32: block = (bd, which, chunk); chunk handles rows 32c..32c+31.
// ---------------------------------------------------------------------------
__device__ __forceinline__ float4 hconv(float4 c, float m1, float m2,
                                        float w0, float w1, float w2) {
    float4 o;
    o.x = w0 * m2  + w1 * m1  + w2 * c.x;
    o.y = w0 * m1  + w1 * c.x + w2 * c.y;
    o.z = w0 * c.x + w1 * c.y + w2 * c.z;
    o.w = w0 * c.y + w1 * c.z + w2 * c.w;
    return o;
}
__device__ __forceinline__ void lnbr(float4 c, int lane, float& m1, float& m2) {
    m1 = __shfl_up_sync(0xFFFFFFFFu, c.w, 1);
    m2 = __shfl_up_sync(0xFFFFFFFFu, c.z, 1);
    if (lane == 0) { m1 = 0.f; m2 = 0.f; }
}

__global__ __launch_bounds__(32) void dwconv_kernel(
    const float* __restrict__ sfw, const float* __restrict__ sfb)
{
    const int blk = blockIdx.x;
    const int chunk = blk & 3;
    const int which = (blk >> 2) & 1;
    const int bd = blk >> 3;
    const int b = bd >> 8, d = bd & 255;
    const int lane = threadIdx.x;
    const size_t outp = (size_t)bd << 14;
    const int r0 = chunk * 32;

    if (which == 0) {
        const float* p = g_U + ((size_t)(b * 768 + d) << 14);
        float w[9];
        #pragma unroll
        for (int q = 0; q < 9; q++) w[q] = sfw[d * 9 + q];
        const float bs = sfb[d];
        float4 av = {0,0,0,0}, rv = {0,0,0,0};
        float am1 = 0, am2 = 0, rm1 = 0, rm2 = 0;
        if (chunk > 0) {
            av = *(const float4*)(p + (r0 - 2) * 128 + lane * 4);
            lnbr(av, lane, am1, am2);
            rv = *(const float4*)(p + (r0 - 1) * 128 + lane * 4);
            lnbr(rv, lane, rm1, rm2);
        }
        for (int i = r0; i < r0 + 32; i++) {
            float4 cv = *(const float4*)(p + i * 128 + lane * 4);
            float cm1, cm2;
            lnbr(cv, lane, cm1, cm2);
            float4 o = hconv(av, am1, am2, w[0], w[1], w[2]);
            float4 o2 = hconv(rv, rm1, rm2, w[3], w[4], w[5]);
            float4 o3 = hconv(cv, cm1, cm2, w[6], w[7], w[8]);
            float4 r;
            r.x = bs + o.x + o2.x + o3.x;
            r.y = bs + o.y + o2.y + o3.y;
            r.z = bs + o.z + o2.z + o3.z;
            r.w = bs + o.w + o2.w + o3.w;
            *(float4*)(g_x0 + outp + i * 128 + lane * 4) = r;
            av = rv; am1 = rm1; am2 = rm2;
            rv = cv; rm1 = cm1; rm2 = cm2;
        }
    } else {
        const float* p1 = g_U + ((size_t)(b * 768 + 256 + d) << 14);
        const float* p2 = g_U + ((size_t)(b * 768 + 512 + d) << 14);
        float w1[9], w2[9];
        #pragma unroll
        for (int q = 0; q < 9; q++) {
            w1[q] = sfw[(256 + d) * 9 + q];
            w2[q] = sfw[(512 + d) * 9 + q];
        }
        const float bs1 = sfb[256 + d], bs2 = sfb[512 + d];
        float4 av1 = {0,0,0,0}, rv1 = {0,0,0,0}, av2 = {0,0,0,0}, rv2 = {0,0,0,0};
        float am11=0, am12=0, rm11=0, rm12=0, am21=0, am22=0, rm21=0, rm22=0;
        if (chunk > 0) {
            av1 = *(const float4*)(p1 + (r0 - 2) * 128 + lane * 4);
            lnbr(av1, lane, am11, am12);
            rv1 = *(const float4*)(p1 + (r0 - 1) * 128 + lane * 4);
            lnbr(rv1, lane, rm11, rm12);
            av2 = *(const float4*)(p2 + (r0 - 2) * 128 + lane * 4);
            lnbr(av2, lane, am21, am22);
            rv2 = *(const float4*)(p2 + (r0 - 1) * 128 + lane * 4);
            lnbr(rv2, lane, rm21, rm22);
        }
        for (int i = r0; i < r0 + 32; i++) {
            float4 cv1 = *(const float4*)(p1 + i * 128 + lane * 4);
            float4 cv2 = *(const float4*)(p2 + i * 128 + lane * 4);
            float cm11, cm12, cm21, cm22;
            lnbr(cv1, lane, cm11, cm12);
            lnbr(cv2, lane, cm21, cm22);
            float4 oa = hconv(av1, am11, am12, w1[0], w1[1], w1[2]);
            float4 ob = hconv(rv1, rm11, rm12, w1[3], w1[4], w1[5]);
            float4 oc = hconv(cv1, cm11, cm12, w1[6], w1[7], w1[8]);
            float4 pa = hconv(av2, am21, am22, w2[0], w2[1], w2[2]);
            float4 pb = hconv(rv2, rm21, rm22, w2[3], w2[4], w2[5]);
            float4 pc = hconv(cv2, cm21, cm22, w2[6], w2[7], w2[8]);
            float4 r;
            r.x = (bs1 + oa.x + ob.x + oc.x) * (bs2 + pa.x + pb.x + pc.x);
            r.y = (bs1 + oa.y + ob.y + oc.y) * (bs2 + pa.y + pb.y + pc.y);
            r.z = (bs1 + oa.z + ob.z + oc.z) * (bs2 + pa.z + pb.z + pc.z);
            r.w = (bs1 + oa.w + ob.w + oc.w) * (bs2 + pa.w + pb.w + pc.w);
            *(float4*)(g_vg + outp + i * 128 + lane * 4) = r;
            av1 = rv1; am11 = rm11; am12 = rm12;
            rv1 = cv1; rm11 = cm11; rm12 = cm12;
            av2 = rv2; am21 = rm21; am22 = rm22;
            rv2 = cv2; rm21 = cm21; rm22 = cm22;
        }
    }
}

// ---------------------------------------------------------------------------
// Fused Toeplitz, 2 CTAs/SM (109KB smem). Chunked staging, persistent W1.
// ---------------------------------------------------------------------------
#define TW_W1H 0
#define TW_W1L 34816
#define TW_AH  69632
#define TW_AL  79872
#define TW_BH  90112
#define TW_BL  100352
#define TW_HV  110592
#define TW_SMEM 111616

__global__ __launch_bounds__(256) void toep_mma(const float* __restrict__ fbias)
{
    extern __shared__ __align__(16) char sm[];
    const uint32_t smb = smem_u32(sm);
    float* hxs = (float*)(sm + TW_HV);
    float* hys = hxs + 128;
    const int tid = threadIdx.x, lane = tid & 31, wid = tid >> 5;
    const int wm = wid & 1, wn = wid >> 1;
    const int bd = blockIdx.x;
    const int d = bd & 255;
    const float* vgp = g_vg + ((size_t)bd << 14);
    const int aq = tid & 7, ar0 = tid >> 3;

    if (tid < 128) {
        hxs[tid] = g_hxT[d * 128 + tid];
        hys[tid] = g_hyT[d * 128 + tid];
    }
    __syncthreads();

    float acc[4][4][4];
    #pragma unroll
    for (int a = 0; a < 4; a++)
        #pragma unroll
        for (int b = 0; b < 4; b++)
            #pragma unroll
            for (int c = 0; c < 4; c++) acc[a][b][c] = 0.f;

    // ---- pass 1: W1 = VG @ T(hy), 4 chunks of k=32 ----
    for (int kc = 0; kc < 4; kc++) {
        if (kc > 0) __syncthreads();
        #pragma unroll
        for (int i = 0; i < 4; i++) {
            int r = ar0 + 32 * i;
            int c = kc * 32 + aq * 4;
            float4 v = *(const float4*)(vgp + r * 128 + c);
            uint2 hv, lv;
            split4(v, hv, lv);
            *(uint2*)(sm + TW_AH + r * 80 + aq * 8) = hv;
            *(uint2*)(sm + TW_AL + r * 80 + aq * 8) = lv;
            float4 t;
            t.x = (r - c     >= 0) ? hys[r - c]     : 0.f;
            t.y = (r - c - 1 >= 0) ? hys[r - c - 1] : 0.f;
            t.z = (r - c - 2 >= 0) ? hys[r - c - 2] : 0.f;
            t.w = (r - c - 3 >= 0) ? hys[r - c - 3] : 0.f;
            split4(t, hv, lv);
            *(uint2*)(sm + TW_BH + r * 80 + aq * 8) = hv;
            *(uint2*)(sm + TW_BL + r * 80 + aq * 8) = lv;
        }
        __syncthreads();
        mma_panel<80, 80>(acc,
            smb + TW_AH + wm * 64 * 80, smb + TW_AL + wm * 64 * 80,
            smb + TW_BH + wn * 32 * 80, smb + TW_BL + wn * 32 * 80, lane, 2);
    }
    __syncthreads();

    // W1^T split -> persistent W1 region (stride 136)
    __nv_bfloat16* bh = (__nv_bfloat16*)(sm + TW_W1H);
    __nv_bfloat16* bl = (__nv_bfloat16*)(sm + TW_W1L);
    #pragma unroll
    for (int mt = 0; mt < 4; mt++)
        #pragma unroll
        for (int nt = 0; nt < 4; nt++) {
            int m = wm * 64 + mt * 16 + (lane >> 2);
            int n = wn * 32 + nt * 8 + 2 * (lane & 3);
            unsigned short h, l;
            split_bf16(acc[mt][nt][0], h, l);
            bh[n * 136 + m] = __ushort_as_bfloat16(h);
            bl[n * 136 + m] = __ushort_as_bfloat16(l);
            split_bf16(acc[mt][nt][1], h, l);
            bh[(n + 1) * 136 + m] = __ushort_as_bfloat16(h);
            bl[(n + 1) * 136 + m] = __ushort_as_bfloat16(l);
            split_bf16(acc[mt][nt][2], h, l);
            bh[n * 136 + m + 8] = __ushort_as_bfloat16(h);
            bl[n * 136 + m + 8] = __ushort_as_bfloat16(l);
            split_bf16(acc[mt][nt][3], h, l);
            bh[(n + 1) * 136 + m + 8] = __ushort_as_bfloat16(h);
            bl[(n + 1) * 136 + m + 8] = __ushort_as_bfloat16(l);
            acc[mt][nt][0] = acc[mt][nt][1] = acc[mt][nt][2] = acc[mt][nt][3] = 0.f;
        }

    // ---- pass 2: C = T(hx) @ W1 ----
    for (int kc = 0; kc < 4; kc++) {
        __syncthreads();
        #pragma unroll
        for (int i = 0; i < 4; i++) {
            int r = ar0 + 32 * i;
            int c = kc * 32 + aq * 4;
            float4 t;
            t.x = (r - c     >= 0) ? hxs[r - c]     : 0.f;
            t.y = (r - c - 1 >= 0) ? hxs[r - c - 1] : 0.f;
            t.z = (r - c - 2 >= 0) ? hxs[r - c - 2] : 0.f;
            t.w = (r - c - 3 >= 0) ? hxs[r - c - 3] : 0.f;
            uint2 hv, lv;
            split4(t, hv, lv);
            *(uint2*)(sm + TW_AH + r * 80 + aq * 8) = hv;
            *(uint2*)(sm + TW_AL + r * 80 + aq * 8) = lv;
        }
        __syncthreads();
        mma_panel<80, 272>(acc,
            smb + TW_AH + wm * 64 * 80, smb + TW_AL + wm * 64 * 80,
            smb + TW_W1H + wn * 32 * 272 + kc * 64,
            smb + TW_W1L + wn * 32 * 272 + kc * 64, lane, 2);
    }

    // epilogue: g = (C + vg*fb) * x0
    const float fb = fbias[d];
    const float* x0p = g_x0 + ((size_t)bd << 14);
    float* gp = g_g + ((size_t)bd << 14);
    #pragma unroll
    for (int mt = 0; mt < 4; mt++)
        #pragma unroll
        for (int nt = 0; nt < 4; nt++) {
            int m = wm * 64 + mt * 16 + (lane >> 2);
            int n = wn * 32 + nt * 8 + 2 * (lane & 3);
            #pragma unroll
            for (int half = 0; half < 2; half++) {
                int idx = (m + 8 * half) * 128 + n;
                float2 c = { acc[mt][nt][2 * half], acc[mt][nt][2 * half + 1] };
                float2 v = *(const float2*)(vgp + idx);
                float2 x = *(const float2*)(x0p + idx);
                float2 r;
                r.x = (c.x + v.x * fb) * x.x;
                r.y = (c.y + v.y * fb) * x.y;
                *(float2*)(gp + idx) = r;
            }
        }
}

// ---------------------------------------------------------------------------
extern "C" void kernel_launch(void* const* d_in, const int* in_sizes, int n_in,
                              void* d_out, int out_size)
{
    (void)in_sizes; (void)n_in; (void)out_size;
    const float* x     = (const float*)d_in[0];
    const float* in_w  = (const float*)d_in[1];
    const float* in_b  = (const float*)d_in[2];
    const float* out_w = (const float*)d_in[3];
    const float* out_b = (const float*)d_in[4];
    const float* sf_w  = (const float*)d_in[5];
    const float* sf_b  = (const float*)d_in[6];
    const float* freq  = (const float*)d_in[7];
    const float* xw0 = (const float*)d_in[8];
    const float* xb0 = (const float*)d_in[9];
    const float* xw1 = (const float*)d_in[10];
    const float* xb1 = (const float*)d_in[11];
    const float* xw2 = (const float*)d_in[12];
    const float* xb2 = (const float*)d_in[13];
    const float* xw3 = (const float*)d_in[14];
    const float* yw0 = (const float*)d_in[15];
    const float* yb0 = (const float*)d_in[16];
    const float* yw1 = (const float*)d_in[17];
    const float* yb1 = (const float*)d_in[18];
    const float* yw2 = (const float*)d_in[19];
    const float* yb2 = (const float*)d_in[20];
    const float* yw3 = (const float*)d_in[21];
    const float* fbias = (const float*)d_in[22];
    float* out = (float*)d_out;

    cudaFuncSetAttribute(gemm1_mma, cudaFuncAttributeMaxDynamicSharedMemorySize, G1_SMEM);
    cudaFuncSetAttribute(gemm2_mma, cudaFuncAttributeMaxDynamicSharedMemorySize, G2_SMEM);
    cudaFuncSetAttribute(toep_mma,  cudaFuncAttributeMaxDynamicSharedMemorySize, TW_SMEM);

    filter_kernel<<<128, 64>>>(freq, xw0, xb0, xw1, xb1, xw2, xb2, xw3,
                               yw0, yb0, yw1, yb1, yw2, yb2, yw3);
    dim3 tb(32, 8);
    tsplit_kernel<<<dim3(32, 8), tb>>>(in_w, out_w);

    dim3 g1(6, 512);
    gemm1_mma<<<g1, 256, G1_SMEM>>>(x, in_b);

    dwconv_kernel<<<8192, 32>>>(sf_w, sf_b);
    toep_mma<<<1024, 256, TW_SMEM>>>(fbias);

    dim3 g2(2, 128, 4);
    gemm2_mma<<<g2, 256, G2_SMEM>>>(out_b, out);
}